// round 5
// baseline (speedup 1.0000x reference)
#include <cuda_runtime.h>
#include <cstdint>

#define Bsz  4096
#define Tst  128
#define NL   256
#define NOt  32
#define Vt   64
#define KB   32         // k per W1 stage
#define NST  8          // 256/KB stages
#define MT   32         // batch rows per CTA
#define SX   36         // xs row stride
#define SLG  36
#define WCOL 16         // W1 cols owned per warp

typedef unsigned long long ull;

__device__ __forceinline__ ull pk2(float lo, float hi) {
    ull r; asm("mov.b64 %0, {%1, %2};" : "=l"(r) : "f"(lo), "f"(hi)); return r;
}
__device__ __forceinline__ float2 upk2(ull v) {
    float2 r; asm("mov.b64 {%0, %1}, %2;" : "=f"(r.x), "=f"(r.y) : "l"(v)); return r;
}
__device__ __forceinline__ void fma2(ull &d, ull a, ull b) {
    asm("fma.rn.f32x2 %0, %1, %2, %0;" : "+l"(d) : "l"(a), "l"(b));
}

// smem float offsets
#define OF_XS0  0
#define OF_XS1  (OF_XS0 + NL * SX)           //  9216
#define OF_WS   (OF_XS1 + NL * SX)           // 18432 : 16 warps x [2][KB][16]
#define OF_W2   (OF_WS + 16 * 2 * KB * WCOL) // 34816 : [NL][32] k-major
#define OF_LG   (OF_W2 + NL * 32)            // 43008 : [32][SLG]
#define OF_YB   (OF_LG + 32 * SLG)           // 44160 : [16][64]
#define OF_B2   (OF_YB + 16 * 64)            // 45184
#define OF_SQ   (OF_B2 + 32)                 // 45216
#define SMEMF   (OF_SQ + 128)                // 45344 floats = 181376 B

__global__ void __launch_bounds__(512, 1) lalr_all(
    const float* __restrict__ latent0,
    const float* __restrict__ W1, const float* __restrict__ b1,
    const float* __restrict__ W2, const float* __restrict__ b2,
    const int*   __restrict__ state_seq, const int* __restrict__ out_idx,
    float* __restrict__ out)
{
    extern __shared__ float sm[];
    float* w2s = sm + OF_W2;
    float* lg  = sm + OF_LG;
    float* yb  = sm + OF_YB;
    float* b2s = sm + OF_B2;
    int*  sseq = (int*)(sm + OF_SQ);

    const int tid = threadIdx.x;
    const int w = tid >> 5, l = tid & 31;
    const int rowbase = blockIdx.x * MT;

    // GEMM1 mapping: warp owns cols [16w,16w+16); lane tile: 4 rows x 4 cols
    const int rg2 = (l >> 2) * 4;           // 0,4,...,28 : rows rg2..rg2+3
    const int cf  = (l & 3) * 4;            // 0,4,8,12
    const int c0  = w * WCOL + cf;          // 4 cols c0..c0+3
    float* wsw = sm + OF_WS + w * (2 * KB * WCOL);   // warp-private W1 stage

    // W1 stage-fill mapping (warp-local): lane -> col r1f in [0,16), k-half
    const int r1f = l >> 1;
    const int khf = (l & 1) * 16;

    // GEMM2 mapping
    const int r2  = tid >> 4;
    const int kh2 = (tid >> 3) & 1;
    const int oq  = tid & 7;

    // W2 fill mapping
    const int o2  = tid & 31;
    const int kq2 = (tid >> 5) * 16;

    // ---- init ----
    if (tid < Tst) sseq[tid] = state_seq[tid];
    {
        float* xs0 = sm + OF_XS0;
        int r = tid >> 4, kq = (tid & 15) * 16;
        const float* src = latent0 + (size_t)(rowbase + r) * NL + kq;
        #pragma unroll
        for (int j = 0; j < 4; j++) {
            float4 v = *(const float4*)(src + j * 4);
            int k = kq + j * 4;
            xs0[(k + 0) * SX + r] = v.x;
            xs0[(k + 1) * SX + r] = v.y;
            xs0[(k + 2) * SX + r] = v.z;
            xs0[(k + 3) * SX + r] = v.w;
        }
    }
    __syncthreads();

    // ---- prologue loads for t=0 ----
    int s = sseq[0];
    const float* w1src = W1 + (size_t)s * NL * NL + (size_t)(w * WCOL + r1f) * NL + khf;
    float4 p0 = *(const float4*)(w1src + 0);
    float4 p1 = *(const float4*)(w1src + 4);
    float4 p2 = *(const float4*)(w1src + 8);
    float4 p3 = *(const float4*)(w1src + 12);
    const float* w2src = W2 + (size_t)s * NOt * NL + (size_t)o2 * NL + kq2;
    float4 q0 = *(const float4*)(w2src + 0);
    float4 q1 = *(const float4*)(w2src + 4);
    float4 q2 = *(const float4*)(w2src + 8);
    float4 q3 = *(const float4*)(w2src + 12);
    float b2r = (tid < NOt) ? b2[s * NOt + tid] : 0.f;

    for (int t = 0; t < Tst; t++) {
        const float* xs_cur = sm + ((t & 1) ? OF_XS1 : OF_XS0);
        float*       xs_nxt = sm + ((t & 1) ? OF_XS0 : OF_XS1);

        float4 b1v = *(const float4*)(b1 + s * NL + c0);
        int idxv = out_idx[s * NOt + l];

        // publish W1 stage 0 (warp-private) and W2 (block-shared)
        {
            float* d = wsw;
            d[(khf + 0) * WCOL + r1f] = p0.x;  d[(khf + 1) * WCOL + r1f] = p0.y;
            d[(khf + 2) * WCOL + r1f] = p0.z;  d[(khf + 3) * WCOL + r1f] = p0.w;
            d[(khf + 4) * WCOL + r1f] = p1.x;  d[(khf + 5) * WCOL + r1f] = p1.y;
            d[(khf + 6) * WCOL + r1f] = p1.z;  d[(khf + 7) * WCOL + r1f] = p1.w;
            d[(khf + 8) * WCOL + r1f] = p2.x;  d[(khf + 9) * WCOL + r1f] = p2.y;
            d[(khf + 10) * WCOL + r1f] = p2.z; d[(khf + 11) * WCOL + r1f] = p2.w;
            d[(khf + 12) * WCOL + r1f] = p3.x; d[(khf + 13) * WCOL + r1f] = p3.y;
            d[(khf + 14) * WCOL + r1f] = p3.z; d[(khf + 15) * WCOL + r1f] = p3.w;
        }
        // prefetch W1 stage 1
        p0 = *(const float4*)(w1src + KB + 0);
        p1 = *(const float4*)(w1src + KB + 4);
        p2 = *(const float4*)(w1src + KB + 8);
        p3 = *(const float4*)(w1src + KB + 12);
        // W2 -> smem k-major
        #pragma unroll
        for (int i = 0; i < 4; i++) {
            w2s[(kq2 + 0 + i) * 32 + o2]  = ((const float*)&q0)[i];
            w2s[(kq2 + 4 + i) * 32 + o2]  = ((const float*)&q1)[i];
            w2s[(kq2 + 8 + i) * 32 + o2]  = ((const float*)&q2)[i];
            w2s[(kq2 + 12 + i) * 32 + o2] = ((const float*)&q3)[i];
        }
        if (tid < NOt) b2s[tid] = b2r;
        __syncwarp();

        // ---- GEMM1 (no block barriers): acc[2 row-pairs][4 cols] ----
        ull acc[2][4];
        #pragma unroll
        for (int c = 0; c < 4; c++) { acc[0][c] = 0ull; acc[1][c] = 0ull; }

        for (int kt = 0; kt < NST; kt++) {
            const float* wp = wsw + (kt & 1) * KB * WCOL + cf;
            const float* xp = xs_cur + (kt * KB) * SX + rg2;
            #pragma unroll 8
            for (int kk = 0; kk < KB; kk++) {
                ulonglong2 X = *(const ulonglong2*)(xp);   // rows rg2..rg2+3
                float4 w4 = *(const float4*)(wp);
                ull wa = pk2(w4.x, w4.x);
                ull wb = pk2(w4.y, w4.y);
                ull wc = pk2(w4.z, w4.z);
                ull wd = pk2(w4.w, w4.w);
                fma2(acc[0][0], X.x, wa); fma2(acc[1][0], X.y, wa);
                fma2(acc[0][1], X.x, wb); fma2(acc[1][1], X.y, wb);
                fma2(acc[0][2], X.x, wc); fma2(acc[1][2], X.y, wc);
                fma2(acc[0][3], X.x, wd); fma2(acc[1][3], X.y, wd);
                xp += SX; wp += WCOL;
            }
            if (kt + 1 < NST) {
                float* d = wsw + ((kt + 1) & 1) * KB * WCOL;
                d[(khf + 0) * WCOL + r1f] = p0.x;  d[(khf + 1) * WCOL + r1f] = p0.y;
                d[(khf + 2) * WCOL + r1f] = p0.z;  d[(khf + 3) * WCOL + r1f] = p0.w;
                d[(khf + 4) * WCOL + r1f] = p1.x;  d[(khf + 5) * WCOL + r1f] = p1.y;
                d[(khf + 6) * WCOL + r1f] = p1.z;  d[(khf + 7) * WCOL + r1f] = p1.w;
                d[(khf + 8) * WCOL + r1f] = p2.x;  d[(khf + 9) * WCOL + r1f] = p2.y;
                d[(khf + 10) * WCOL + r1f] = p2.z; d[(khf + 11) * WCOL + r1f] = p2.w;
                d[(khf + 12) * WCOL + r1f] = p3.x; d[(khf + 13) * WCOL + r1f] = p3.y;
                d[(khf + 14) * WCOL + r1f] = p3.z; d[(khf + 15) * WCOL + r1f] = p3.w;
                if (kt + 2 < NST) {
                    const float* src = w1src + (kt + 2) * KB;
                    p0 = *(const float4*)(src + 0);
                    p1 = *(const float4*)(src + 4);
                    p2 = *(const float4*)(src + 8);
                    p3 = *(const float4*)(src + 12);
                }
                __syncwarp();
            }
        }

        // ---- tail prefetch for step t+1 ----
        s = sseq[(t + 1) & (Tst - 1)];
        w1src = W1 + (size_t)s * NL * NL + (size_t)(w * WCOL + r1f) * NL + khf;
        p0 = *(const float4*)(w1src + 0);
        p1 = *(const float4*)(w1src + 4);
        p2 = *(const float4*)(w1src + 8);
        p3 = *(const float4*)(w1src + 12);
        w2src = W2 + (size_t)s * NOt * NL + (size_t)o2 * NL + kq2;
        q0 = *(const float4*)(w2src + 0);
        q1 = *(const float4*)(w2src + 4);
        q2 = *(const float4*)(w2src + 8);
        q3 = *(const float4*)(w2src + 12);
        b2r = (tid < NOt) ? b2[s * NOt + tid] : 0.f;

        // ---- epilogue: tanh -> xs_nxt (k-major), 4 STS.128 per lane ----
        #pragma unroll
        for (int c = 0; c < 4; c++) {
            float bb = ((const float*)&b1v)[c];
            float2 u0 = upk2(acc[0][c]);   // rows rg2, rg2+1
            float2 u1 = upk2(acc[1][c]);   // rows rg2+2, rg2+3
            float4 v;
            v.x = tanhf(u0.x + bb); v.y = tanhf(u0.y + bb);
            v.z = tanhf(u1.x + bb); v.w = tanhf(u1.y + bb);
            *(float4*)(xs_nxt + (c0 + c) * SX + rg2) = v;
        }
        __syncthreads();

        // ---- GEMM2: logits = x_new @ W2^T + b2 (split-k 2) ----
        {
            ull a0 = 0ull, a1 = 0ull;
            const float* xq = xs_nxt + (kh2 * 128) * SX + r2;
            const float* wq = w2s + (kh2 * 128) * 32 + oq * 4;
            #pragma unroll 8
            for (int i = 0; i < 128; i++) {
                float xv = *xq;
                ull xx = pk2(xv, xv);
                ulonglong2 wv = *(const ulonglong2*)(wq);
                fma2(a0, xx, wv.x);
                fma2(a1, xx, wv.y);
                xq += SX; wq += 32;
            }
            ull m0 = __shfl_xor_sync(0xffffffffu, a0, 8);
            ull m1 = __shfl_xor_sync(0xffffffffu, a1, 8);
            if (kh2 == 0) {
                float2 A0 = upk2(a0), A1 = upk2(a1);
                float2 P0 = upk2(m0), P1 = upk2(m1);
                float4 r4;
                r4.x = A0.x + P0.x + b2s[oq * 4 + 0];
                r4.y = A0.y + P0.y + b2s[oq * 4 + 1];
                r4.z = A1.x + P1.x + b2s[oq * 4 + 2];
                r4.w = A1.y + P1.y + b2s[oq * 4 + 3];
                *(float4*)(lg + r2 * SLG + oq * 4) = r4;
            }
        }
        __syncthreads();

        // ---- softmax + last-write-wins scatter + out ----
        {
            float* y = yb + w * 64;
            unsigned mset = __match_any_sync(0xffffffffu, idxv);
            bool leader = (31 - __clz(mset)) == l;
            #pragma unroll
            for (int rr = 0; rr < 2; rr++) {
                int row = w * 2 + rr;
                float v = lg[row * SLG + l];
                float m = v;
                #pragma unroll
                for (int off = 16; off > 0; off >>= 1)
                    m = fmaxf(m, __shfl_xor_sync(0xffffffffu, m, off));
                float e = __expf(v - m);
                float ssum = e;
                #pragma unroll
                for (int off = 16; off > 0; off >>= 1)
                    ssum += __shfl_xor_sync(0xffffffffu, ssum, off);
                float p = e / ssum;
                y[l] = 0.f; y[l + 32] = 0.f;
                __syncwarp();
                if (leader) y[idxv] = p;
                __syncwarp();
                float* op = out + (size_t)(rowbase + row) * (Tst * Vt) + (size_t)t * Vt;
                *(float2*)(op + 2 * l) = *(const float2*)(y + 2 * l);
                __syncwarp();
            }
        }
        // next-step smem writes are gated by this step's two __syncthreads
    }
}

extern "C" void kernel_launch(void* const* d_in, const int* in_sizes, int n_in,
                              void* d_out, int out_size)
{
    const float* latent0   = (const float*)d_in[0];
    const float* W1        = (const float*)d_in[1];
    const float* b1        = (const float*)d_in[2];
    const float* W2        = (const float*)d_in[3];
    const float* b2        = (const float*)d_in[4];
    const int*   state_seq = (const int*)  d_in[5];
    const int*   out_idx   = (const int*)  d_in[6];
    float* out = (float*)d_out;

    const int smem_bytes = SMEMF * (int)sizeof(float);   // ~177 KB
    cudaFuncSetAttribute(lalr_all, cudaFuncAttributeMaxDynamicSharedMemorySize, smem_bytes);

    lalr_all<<<Bsz / MT, 512, smem_bytes>>>(
        latent0, W1, b1, W2, b2, state_seq, out_idx, out);
}

// round 7
// speedup vs baseline: 1.2911x; 1.2911x over previous
#include <cuda_runtime.h>
#include <cuda_bf16.h>
#include <cstdint>

#define Bsz 4096
#define Tst 128
#define NL  256
#define NSt 64
#define NOt 32
#define Vt  64
#define MT  32
#define XR  264        // x row stride (bf16 elems)
#define NCH 16         // K chunks of 16
#define SLG 36

typedef unsigned long long ull;
typedef uint32_t u32;

// Pre-split W1 (bf16 hi/lo), filled by a pre-pass kernel each launch.
__device__ __nv_bfloat16 g_w1h[(size_t)NSt * NL * NL];
__device__ __nv_bfloat16 g_w1l[(size_t)NSt * NL * NL];

// ---- helpers ----
__device__ __forceinline__ ull pk2(float lo, float hi) {
    ull r; asm("mov.b64 %0, {%1, %2};" : "=l"(r) : "f"(lo), "f"(hi)); return r;
}
__device__ __forceinline__ float2 upk2(ull v) {
    float2 r; asm("mov.b64 {%0, %1}, %2;" : "=f"(r.x), "=f"(r.y) : "l"(v)); return r;
}
__device__ __forceinline__ void fma2(ull &d, ull a, ull b) {
    asm("fma.rn.f32x2 %0, %1, %2, %0;" : "+l"(d) : "l"(a), "l"(b));
}
__device__ __forceinline__ u32 s2u(const void* p) {
    return (u32)__cvta_generic_to_shared(p);
}
__device__ __forceinline__ void ldsm4(u32* r, u32 a) {
    asm volatile("ldmatrix.sync.aligned.m8n8.x4.shared.b16 {%0,%1,%2,%3}, [%4];"
        : "=r"(r[0]), "=r"(r[1]), "=r"(r[2]), "=r"(r[3]) : "r"(a));
}
__device__ __forceinline__ void mma16(float* c, const u32* a, u32 b0, u32 b1) {
    asm volatile("mma.sync.aligned.m16n8k16.row.col.f32.bf16.bf16.f32 "
        "{%0,%1,%2,%3},{%4,%5,%6,%7},{%8,%9},{%0,%1,%2,%3};"
        : "+f"(c[0]), "+f"(c[1]), "+f"(c[2]), "+f"(c[3])
        : "r"(a[0]), "r"(a[1]), "r"(a[2]), "r"(a[3]), "r"(b0), "r"(b1));
}
// bf16 hi/lo split pair store
__device__ __forceinline__ void sp(__nv_bfloat16* xh, __nv_bfloat16* xl, int idx,
                                   float v0, float v1) {
    __nv_bfloat16 h0 = __float2bfloat16(v0), h1 = __float2bfloat16(v1);
    __nv_bfloat162 hp; hp.x = h0; hp.y = h1;
    *(__nv_bfloat162*)(xh + idx) = hp;
    __nv_bfloat162 lp;
    lp.x = __float2bfloat16(v0 - __bfloat162float(h0));
    lp.y = __float2bfloat16(v1 - __bfloat162float(h1));
    *(__nv_bfloat162*)(xl + idx) = lp;
}

// smem byte offsets
#define OB_XH  0
#define OB_XL  (OB_XH + 2 * 32 * XR * 2)     // 33792
#define OB_W1S (OB_XL + 2 * 32 * XR * 2)     // 67584 : 16 warps x 2buf x 2arr x 768B
#define OB_W2  (OB_W1S + 16 * 2 * 2 * 768)   // 116736 : [NL][32] f32
#define OB_LG  (OB_W2 + NL * 32 * 4)         // 149504
#define OB_YB  (OB_LG + 32 * SLG * 4)        // 154112
#define OB_B2  (OB_YB + 16 * 64 * 4)         // 158208
#define OB_SQ  (OB_B2 + 128)                 // 158336
#define SMEMB  (OB_SQ + 512)                 // 158848 B

__global__ void split_w1(const float* __restrict__ W1) {
    const size_t n = (size_t)NSt * NL * NL;
    for (size_t i = blockIdx.x * blockDim.x + threadIdx.x; i < n;
         i += (size_t)gridDim.x * blockDim.x) {
        float x = W1[i];
        __nv_bfloat16 h = __float2bfloat16(x);
        g_w1h[i] = h;
        g_w1l[i] = __float2bfloat16(x - __bfloat162float(h));
    }
}

__global__ void __launch_bounds__(512, 1) lalr_all(
    const float* __restrict__ latent0,
    const float* __restrict__ W1, const float* __restrict__ b1,
    const float* __restrict__ W2, const float* __restrict__ b2,
    const int*   __restrict__ state_seq, const int* __restrict__ out_idx,
    float* __restrict__ out)
{
    extern __shared__ char smc[];
    __nv_bfloat16* xh = (__nv_bfloat16*)(smc + OB_XH);   // [2][32][XR]
    __nv_bfloat16* xl = (__nv_bfloat16*)(smc + OB_XL);
    float* w2s = (float*)(smc + OB_W2);                  // [NL][32]
    float* lg  = (float*)(smc + OB_LG);
    float* yb  = (float*)(smc + OB_YB);
    float* b2s = (float*)(smc + OB_B2);
    int*  sseq = (int*)(smc + OB_SQ);

    const int tid = threadIdx.x;
    const int w = tid >> 5, l = tid & 31;
    const int rowbase = blockIdx.x * MT;
    const int gid = l >> 2, tg = l & 3;

    // ldmatrix lane mappings
    const int arow = l & 15;               // A: row within m-tile
    const int akof = (l >> 4) * 8;         // A: k offset (0/8)
    const int bofs = (((((l >> 4) & 1) * 8) + (l & 7)) * 24 + ((l >> 3) & 1) * 8) * 2;
    // W1 stage fill mapping
    const int fn = l & 15;                 // n (col) within warp slice
    const int fk = (l >> 4) * 8;           // k offset within chunk
    char* wbase = smc + OB_W1S + w * 3072; // 2buf x 2arr x 768B
    const int stsofs = (fn * 24 + fk) * 2;
    // W2 fill / GEMM2 mappings
    const int o2 = tid & 31, kq2 = (tid >> 5) * 16;
    const int r2 = tid >> 4, kh2 = (tid >> 3) & 1, oq = tid & 7;

    // ---- init: sseq + latent0 -> bf16 hi/lo buf0 ----
    if (tid < Tst) sseq[tid] = state_seq[tid];
    {
        int r = tid >> 4, kc = (tid & 15) * 16;
        const float* src = latent0 + (size_t)(rowbase + r) * NL + kc;
        __nv_bfloat16* xhp = xh + r * XR + kc;
        __nv_bfloat16* xlp = xl + r * XR + kc;
        #pragma unroll
        for (int j = 0; j < 16; j += 2) {
            float a = src[j], b = src[j + 1];
            sp(xhp, xlp, j, a, b);   // split only (no tanh on step-0 input)
        }
    }
    __syncthreads();

    // ---- prologue loads for t=0 ----
    int s = sseq[0];
    size_t w1o = ((size_t)s * NL + w * 16 + fn) * NL + fk;
    uint4 ph = *(const uint4*)(g_w1h + w1o);
    uint4 pl = *(const uint4*)(g_w1l + w1o);
    const float* w2src = W2 + ((size_t)s * NOt + o2) * NL + kq2;
    float4 q0 = *(const float4*)(w2src + 0);
    float4 q1 = *(const float4*)(w2src + 4);
    float4 q2 = *(const float4*)(w2src + 8);
    float4 q3 = *(const float4*)(w2src + 12);
    float b2r = (tid < NOt) ? b2[s * NOt + tid] : 0.f;

    for (int t = 0; t < Tst; t++) {
        __nv_bfloat16* xh_cur = xh + (t & 1) * 32 * XR;
        __nv_bfloat16* xl_cur = xl + (t & 1) * 32 * XR;
        __nv_bfloat16* xh_nxt = xh + ((t + 1) & 1) * 32 * XR;
        __nv_bfloat16* xl_nxt = xl + ((t + 1) & 1) * 32 * XR;

        float2 bias0 = *(const float2*)(b1 + s * NL + w * 16 + 2 * tg);
        float2 bias1 = *(const float2*)(b1 + s * NL + w * 16 + 8 + 2 * tg);
        int idxv = out_idx[s * NOt + l];

        // publish W1 stage 0 (warp-private)
        *(uint4*)(wbase + stsofs)       = ph;
        *(uint4*)(wbase + 768 + stsofs) = pl;
        // prefetch stage 1
        ph = *(const uint4*)(g_w1h + w1o + 16);
        pl = *(const uint4*)(g_w1l + w1o + 16);
        // W2 -> smem k-major, b2
        #pragma unroll
        for (int i = 0; i < 4; i++) {
            w2s[(kq2 + 0 + i) * 32 + o2]  = ((const float*)&q0)[i];
            w2s[(kq2 + 4 + i) * 32 + o2]  = ((const float*)&q1)[i];
            w2s[(kq2 + 8 + i) * 32 + o2]  = ((const float*)&q2)[i];
            w2s[(kq2 + 12 + i) * 32 + o2] = ((const float*)&q3)[i];
        }
        if (tid < NOt) b2s[tid] = b2r;
        __syncwarp();

        // ---- GEMM1: bf16 4-term split MMA ----
        float acc[2][2][4];
        #pragma unroll
        for (int mi = 0; mi < 2; mi++)
            #pragma unroll
            for (int ni = 0; ni < 2; ni++)
                #pragma unroll
                for (int j = 0; j < 4; j++) acc[mi][ni][j] = 0.f;

        const u32 aHb = s2u(xh_cur + arow * XR + akof);
        const u32 aLb = s2u(xl_cur + arow * XR + akof);

        for (int kt = 0; kt < NCH; kt++) {
            const u32 ka = kt * 32;               // 16 halfs per chunk
            u32 ah0[4], ah1[4], al0[4], al1[4], bh[4], bl[4];
            ldsm4(ah0, aHb + ka);
            ldsm4(ah1, aHb + ka + 16 * XR * 2);
            ldsm4(al0, aLb + ka);
            ldsm4(al1, aLb + ka + 16 * XR * 2);
            char* wb = wbase + (kt & 1) * 1536;
            // W1 stage is [n][k] k-contiguous == K x N col-major: NON-trans
            // ldmatrix yields exactly the mma .col B fragment (R6 bug was .trans)
            ldsm4(bh, s2u(wb) + bofs);
            ldsm4(bl, s2u(wb + 768) + bofs);

            mma16(acc[0][0], ah0, bh[0], bh[1]); mma16(acc[0][1], ah0, bh[2], bh[3]);
            mma16(acc[1][0], ah1, bh[0], bh[1]); mma16(acc[1][1], ah1, bh[2], bh[3]);
            mma16(acc[0][0], ah0, bl[0], bl[1]); mma16(acc[0][1], ah0, bl[2], bl[3]);
            mma16(acc[1][0], ah1, bl[0], bl[1]); mma16(acc[1][1], ah1, bl[2], bl[3]);
            mma16(acc[0][0], al0, bh[0], bh[1]); mma16(acc[0][1], al0, bh[2], bh[3]);
            mma16(acc[1][0], al1, bh[0], bh[1]); mma16(acc[1][1], al1, bh[2], bh[3]);
            mma16(acc[0][0], al0, bl[0], bl[1]); mma16(acc[0][1], al0, bl[2], bl[3]);
            mma16(acc[1][0], al1, bl[0], bl[1]); mma16(acc[1][1], al1, bl[2], bl[3]);

            if (kt + 1 < NCH) {
                char* d = wbase + ((kt + 1) & 1) * 1536;
                *(uint4*)(d + stsofs)       = ph;
                *(uint4*)(d + 768 + stsofs) = pl;
                if (kt + 2 < NCH) {
                    ph = *(const uint4*)(g_w1h + w1o + (size_t)(kt + 2) * 16);
                    pl = *(const uint4*)(g_w1l + w1o + (size_t)(kt + 2) * 16);
                }
                __syncwarp();
            }
        }

        // ---- tail prefetch for t+1 ----
        s = sseq[(t + 1) & (Tst - 1)];
        w1o = ((size_t)s * NL + w * 16 + fn) * NL + fk;
        ph = *(const uint4*)(g_w1h + w1o);
        pl = *(const uint4*)(g_w1l + w1o);
        w2src = W2 + ((size_t)s * NOt + o2) * NL + kq2;
        q0 = *(const float4*)(w2src + 0);
        q1 = *(const float4*)(w2src + 4);
        q2 = *(const float4*)(w2src + 8);
        q3 = *(const float4*)(w2src + 12);
        b2r = (tid < NOt) ? b2[s * NOt + tid] : 0.f;

        // ---- epilogue: tanh + bf16 split -> x_next ----
        #pragma unroll
        for (int mi = 0; mi < 2; mi++)
            #pragma unroll
            for (int ni = 0; ni < 2; ni++) {
                float2 bias = ni ? bias1 : bias0;
                float* c = acc[mi][ni];
                int cp = w * 16 + ni * 8 + 2 * tg;
                int r0 = mi * 16 + gid;
                sp(xh_nxt, xl_nxt, r0 * XR + cp,
                   tanhf(c[0] + bias.x), tanhf(c[1] + bias.y));
                sp(xh_nxt, xl_nxt, (r0 + 8) * XR + cp,
                   tanhf(c[2] + bias.x), tanhf(c[3] + bias.y));
            }
        __syncthreads();

        // ---- GEMM2: logits = (xh+xl) @ W2^T + b2 (split-k 2) ----
        {
            ull a0 = 0ull, a1 = 0ull;
            const __nv_bfloat16* xhp = xh_nxt + r2 * XR + kh2 * 128;
            const __nv_bfloat16* xlp = xl_nxt + r2 * XR + kh2 * 128;
            const float* wq = w2s + (kh2 * 128) * 32 + oq * 4;
            #pragma unroll 4
            for (int i = 0; i < 64; i++) {
                float2 hf = __bfloat1622float2(*(const __nv_bfloat162*)(xhp + 2 * i));
                float2 lf = __bfloat1622float2(*(const __nv_bfloat162*)(xlp + 2 * i));
                float x0 = hf.x + lf.x, x1 = hf.y + lf.y;
                ulonglong2 w0 = *(const ulonglong2*)(wq);
                ulonglong2 w1 = *(const ulonglong2*)(wq + 32);
                fma2(a0, pk2(x0, x0), w0.x); fma2(a1, pk2(x0, x0), w0.y);
                fma2(a0, pk2(x1, x1), w1.x); fma2(a1, pk2(x1, x1), w1.y);
                wq += 64;
            }
            ull m0 = __shfl_xor_sync(0xffffffffu, a0, 8);
            ull m1 = __shfl_xor_sync(0xffffffffu, a1, 8);
            if (kh2 == 0) {
                float2 A0 = upk2(a0), A1 = upk2(a1);
                float2 P0 = upk2(m0), P1 = upk2(m1);
                float4 r4;
                r4.x = A0.x + P0.x + b2s[oq * 4 + 0];
                r4.y = A0.y + P0.y + b2s[oq * 4 + 1];
                r4.z = A1.x + P1.x + b2s[oq * 4 + 2];
                r4.w = A1.y + P1.y + b2s[oq * 4 + 3];
                *(float4*)(lg + r2 * SLG + oq * 4) = r4;
            }
        }
        __syncthreads();

        // ---- softmax + last-write-wins scatter + out ----
        {
            float* y = yb + w * 64;
            unsigned mset = __match_any_sync(0xffffffffu, idxv);
            bool leader = (31 - __clz(mset)) == l;
            #pragma unroll
            for (int rr = 0; rr < 2; rr++) {
                int row = w * 2 + rr;
                float v = lg[row * SLG + l];
                float m = v;
                #pragma unroll
                for (int off = 16; off > 0; off >>= 1)
                    m = fmaxf(m, __shfl_xor_sync(0xffffffffu, m, off));
                float e = __expf(v - m);
                float ssum = e;
                #pragma unroll
                for (int off = 16; off > 0; off >>= 1)
                    ssum += __shfl_xor_sync(0xffffffffu, ssum, off);
                float p = e / ssum;
                y[l] = 0.f; y[l + 32] = 0.f;
                __syncwarp();
                if (leader) y[idxv] = p;
                __syncwarp();
                float* op = out + (size_t)(rowbase + row) * (Tst * Vt) + (size_t)t * Vt;
                *(float2*)(op + 2 * l) = *(const float2*)(y + 2 * l);
                __syncwarp();
            }
        }
    }
}

extern "C" void kernel_launch(void* const* d_in, const int* in_sizes, int n_in,
                              void* d_out, int out_size)
{
    const float* latent0   = (const float*)d_in[0];
    const float* W1        = (const float*)d_in[1];
    const float* b1        = (const float*)d_in[2];
    const float* W2        = (const float*)d_in[3];
    const float* b2        = (const float*)d_in[4];
    const int*   state_seq = (const int*)  d_in[5];
    const int*   out_idx   = (const int*)  d_in[6];
    float* out = (float*)d_out;

    split_w1<<<2048, 512>>>(W1);

    cudaFuncSetAttribute(lalr_all, cudaFuncAttributeMaxDynamicSharedMemorySize, SMEMB);
    lalr_all<<<Bsz / MT, 512, SMEMB>>>(
        latent0, W1, b1, W2, b2, state_seq, out_idx, out);
}

// round 8
// speedup vs baseline: 2.7577x; 2.1359x over previous
#include <cuda_runtime.h>
#include <cuda_bf16.h>
#include <cstdint>

#define Bsz 4096
#define Tst 128
#define NL  256
#define NSt 64
#define NOt 32
#define Vt  64
#define MT  32
#define XR  264        // x row stride (bf16)
#define NCH 16
#define SLG 36
#define W2R 264        // w2 smem row stride (bf16)

typedef unsigned long long ull;
typedef uint32_t u32;

__device__ __nv_bfloat16 g_w1h[(size_t)NSt * NL * NL];
__device__ __nv_bfloat16 g_w1l[(size_t)NSt * NL * NL];
__device__ __nv_bfloat16 g_w2h[(size_t)NSt * NOt * NL];
__device__ __nv_bfloat16 g_w2l[(size_t)NSt * NOt * NL];

__device__ __forceinline__ u32 s2u(const void* p) {
    return (u32)__cvta_generic_to_shared(p);
}
__device__ __forceinline__ void ldsm4(u32* r, u32 a) {
    asm volatile("ldmatrix.sync.aligned.m8n8.x4.shared.b16 {%0,%1,%2,%3}, [%4];"
        : "=r"(r[0]), "=r"(r[1]), "=r"(r[2]), "=r"(r[3]) : "r"(a));
}
__device__ __forceinline__ void mma16(float* c, const u32* a, u32 b0, u32 b1) {
    asm volatile("mma.sync.aligned.m16n8k16.row.col.f32.bf16.bf16.f32 "
        "{%0,%1,%2,%3},{%4,%5,%6,%7},{%8,%9},{%0,%1,%2,%3};"
        : "+f"(c[0]), "+f"(c[1]), "+f"(c[2]), "+f"(c[3])
        : "r"(a[0]), "r"(a[1]), "r"(a[2]), "r"(a[3]), "r"(b0), "r"(b1));
}
__device__ __forceinline__ void cpa16(u32 dst, const void* src) {
    asm volatile("cp.async.cg.shared.global [%0], [%1], 16;"
        :: "r"(dst), "l"(src) : "memory");
}
#define CPA_COMMIT() asm volatile("cp.async.commit_group;" ::: "memory")
#define CPA_WAIT2()  asm volatile("cp.async.wait_group 2;" ::: "memory")

// bf16 hi/lo split pair store
__device__ __forceinline__ void sp(__nv_bfloat16* xh, __nv_bfloat16* xl, int idx,
                                   float v0, float v1) {
    __nv_bfloat16 h0 = __float2bfloat16(v0), h1 = __float2bfloat16(v1);
    __nv_bfloat162 hp; hp.x = h0; hp.y = h1;
    *(__nv_bfloat162*)(xh + idx) = hp;
    __nv_bfloat162 lp;
    lp.x = __float2bfloat16(v0 - __bfloat162float(h0));
    lp.y = __float2bfloat16(v1 - __bfloat162float(h1));
    *(__nv_bfloat162*)(xl + idx) = lp;
}

// smem byte offsets
#define OB_XH  0                              // [32][XR] bf16   16896
#define OB_XL  16896                          // [32][XR] bf16   16896
#define OB_W1S 33792                          // 16w x 4stage x 2arr x 768B = 98304
#define OB_W2H 132096                         // [32][W2R] bf16  16896
#define OB_W2L 148992                         // 16896
#define OB_RS  165888                         // [8][32][36] f32 36864
#define OB_LG  202752                         // [32][SLG] f32   4608
#define OB_YB  207360                         // [16][64] f32    4096
#define OB_B2  211456                         // 128
#define OB_SQ  211584                         // 512
#define SMEMB  212096

__global__ void split_w12(const float* __restrict__ W1, const float* __restrict__ W2) {
    const size_t n1 = (size_t)NSt * NL * NL;
    for (size_t i = blockIdx.x * blockDim.x + threadIdx.x; i < n1;
         i += (size_t)gridDim.x * blockDim.x) {
        float x = W1[i];
        __nv_bfloat16 h = __float2bfloat16(x);
        g_w1h[i] = h;
        g_w1l[i] = __float2bfloat16(x - __bfloat162float(h));
    }
    const size_t n2 = (size_t)NSt * NOt * NL;
    for (size_t i = blockIdx.x * blockDim.x + threadIdx.x; i < n2;
         i += (size_t)gridDim.x * blockDim.x) {
        float x = W2[i];
        __nv_bfloat16 h = __float2bfloat16(x);
        g_w2h[i] = h;
        g_w2l[i] = __float2bfloat16(x - __bfloat162float(h));
    }
}

__global__ void __launch_bounds__(512, 1) lalr_all(
    const float* __restrict__ latent0,
    const float* __restrict__ W1, const float* __restrict__ b1,
    const float* __restrict__ W2, const float* __restrict__ b2,
    const int*   __restrict__ state_seq, const int* __restrict__ out_idx,
    float* __restrict__ out)
{
    extern __shared__ char smc[];
    __nv_bfloat16* xh = (__nv_bfloat16*)(smc + OB_XH);
    __nv_bfloat16* xl = (__nv_bfloat16*)(smc + OB_XL);
    float* rs  = (float*)(smc + OB_RS);
    float* lg  = (float*)(smc + OB_LG);
    float* yb  = (float*)(smc + OB_YB);
    float* b2s = (float*)(smc + OB_B2);
    int*  sseq = (int*)(smc + OB_SQ);

    const int tid = threadIdx.x;
    const int w = tid >> 5, l = tid & 31;
    const int rowbase = blockIdx.x * MT;
    const int gid = l >> 2, tg = l & 3;

    // ldmatrix lane mappings (proven R7 idioms)
    const int arow = l & 15;
    const int akof = (l >> 4) * 8;
    const int bn   = ((l >> 4) & 1) * 8 + (l & 7);
    const int bk   = (l >> 3) & 1;
    const int bofs24  = (bn * 24  + bk * 8) * 2;   // W1 stage stride 24 halfs
    const int bofs264 = (bn * W2R + bk * 8) * 2;   // W2 smem stride 264 halfs
    // W1 cp.async fill mapping
    const int fn = l & 15;
    const int fk = (l >> 4) * 8;
    const int stsofs = (fn * 24 + fk) * 2;
    const u32 wstage = s2u(smc + OB_W1S + w * 6144);   // 4 stages x 1536B
    char* wbase = smc + OB_W1S + w * 6144;
    // W2 fill mapping
    const int o2 = tid & 31, kq2 = (tid >> 5) * 16;
    // GEMM2 warp roles
    const int mi2 = w & 1, kg = w >> 1;

    // ---- init ----
    if (tid < Tst) sseq[tid] = state_seq[tid];
    {
        int r = tid >> 4, kc = (tid & 15) * 16;
        const float* src = latent0 + (size_t)(rowbase + r) * NL + kc;
        __nv_bfloat16* xhp = xh + r * XR + kc;
        __nv_bfloat16* xlp = xl + r * XR + kc;
        #pragma unroll
        for (int j = 0; j < 16; j += 2) sp(xhp, xlp, j, src[j], src[j + 1]);
    }
    __syncthreads();

    // W1 chunk issuer: global chunk ig -> stage ig&3
    auto issue_w1 = [&](int ig) {
        if (ig < Tst * NCH) {
            int sg = sseq[(ig >> 4) & (Tst - 1)];
            int kc = (ig & 15) << 4;
            size_t off = ((size_t)sg * NL + w * 16 + fn) * NL + kc + fk;
            u32 dh = wstage + (ig & 3) * 1536 + stsofs;
            cpa16(dh, g_w1h + off);
            cpa16(dh + 768, g_w1l + off);
        }
        CPA_COMMIT();
    };
    issue_w1(0); issue_w1(1); issue_w1(2);

    // ---- prologue loads for t=0 ----
    int s = sseq[0];
    const __nv_bfloat16* w2hsrc = g_w2h + ((size_t)s * NOt + o2) * NL + kq2;
    const __nv_bfloat16* w2lsrc = g_w2l + ((size_t)s * NOt + o2) * NL + kq2;
    uint4 qh0 = *(const uint4*)(w2hsrc);
    uint4 qh1 = *(const uint4*)(w2hsrc + 8);
    uint4 ql0 = *(const uint4*)(w2lsrc);
    uint4 ql1 = *(const uint4*)(w2lsrc + 8);
    float b2r = (tid < NOt) ? b2[s * NOt + tid] : 0.f;

    for (int t = 0; t < Tst; t++) {
        float2 bias0 = *(const float2*)(b1 + s * NL + w * 16 + 2 * tg);
        float2 bias1 = *(const float2*)(b1 + s * NL + w * 16 + 8 + 2 * tg);
        int idxv = out_idx[s * NOt + l];

        // W2 -> smem [o][264] bf16 h/l
        {
            char* dh = smc + OB_W2H + (o2 * W2R + kq2) * 2;
            char* dl = smc + OB_W2L + (o2 * W2R + kq2) * 2;
            *(uint4*)(dh) = qh0; *(uint4*)(dh + 16) = qh1;
            *(uint4*)(dl) = ql0; *(uint4*)(dl + 16) = ql1;
        }
        if (tid < NOt) b2s[tid] = b2r;
        __syncwarp();

        // ---- GEMM1: 3-term bf16 split MMA, cp.async pipelined W1 ----
        float acc[2][2][4];
        #pragma unroll
        for (int mi = 0; mi < 2; mi++)
            #pragma unroll
            for (int ni = 0; ni < 2; ni++)
                #pragma unroll
                for (int j = 0; j < 4; j++) acc[mi][ni][j] = 0.f;

        const u32 aHb = s2u(xh + arow * XR + akof);
        const u32 aLb = s2u(xl + arow * XR + akof);

        for (int kt = 0; kt < NCH; kt++) {
            const int g = t * NCH + kt;
            CPA_WAIT2();
            __syncwarp();
            const u32 ka = kt * 32;
            u32 ah0[4], ah1[4], al0[4], al1[4], bh[4], bl[4];
            ldsm4(ah0, aHb + ka);
            ldsm4(ah1, aHb + ka + 16 * XR * 2);
            ldsm4(al0, aLb + ka);
            ldsm4(al1, aLb + ka + 16 * XR * 2);
            char* wb = wbase + (g & 3) * 1536;
            ldsm4(bh, s2u(wb) + bofs24);
            ldsm4(bl, s2u(wb + 768) + bofs24);

            issue_w1(g + 3);

            mma16(acc[0][0], ah0, bh[0], bh[1]); mma16(acc[0][1], ah0, bh[2], bh[3]);
            mma16(acc[1][0], ah1, bh[0], bh[1]); mma16(acc[1][1], ah1, bh[2], bh[3]);
            mma16(acc[0][0], ah0, bl[0], bl[1]); mma16(acc[0][1], ah0, bl[2], bl[3]);
            mma16(acc[1][0], ah1, bl[0], bl[1]); mma16(acc[1][1], ah1, bl[2], bl[3]);
            mma16(acc[0][0], al0, bh[0], bh[1]); mma16(acc[0][1], al0, bh[2], bh[3]);
            mma16(acc[1][0], al1, bh[0], bh[1]); mma16(acc[1][1], al1, bh[2], bh[3]);
        }

        // ---- tail prefetch for t+1 (W2 h/l + b2) ----
        s = sseq[(t + 1) & (Tst - 1)];
        w2hsrc = g_w2h + ((size_t)s * NOt + o2) * NL + kq2;
        w2lsrc = g_w2l + ((size_t)s * NOt + o2) * NL + kq2;
        qh0 = *(const uint4*)(w2hsrc);
        qh1 = *(const uint4*)(w2hsrc + 8);
        ql0 = *(const uint4*)(w2lsrc);
        ql1 = *(const uint4*)(w2lsrc + 8);
        b2r = (tid < NOt) ? b2[s * NOt + tid] : 0.f;

        __syncthreads();   // A: all GEMM1 reads of xh/xl done

        // ---- epilogue: tanh + bf16 split -> xh/xl (in place, x_{t+1}) ----
        #pragma unroll
        for (int mi = 0; mi < 2; mi++)
            #pragma unroll
            for (int ni = 0; ni < 2; ni++) {
                float2 bias = ni ? bias1 : bias0;
                float* c = acc[mi][ni];
                int cp = w * 16 + ni * 8 + 2 * tg;
                int r0 = mi * 16 + gid;
                sp(xh, xl, r0 * XR + cp, tanhf(c[0] + bias.x), tanhf(c[1] + bias.y));
                sp(xh, xl, (r0 + 8) * XR + cp, tanhf(c[2] + bias.x), tanhf(c[3] + bias.y));
            }
        __syncthreads();   // B: x_{t+1} + w2 smem ready

        // ---- GEMM2 via MMA: warp = m16(mi2) x n32 x k32(kg), 3-term ----
        {
            float c2[4][4];
            #pragma unroll
            for (int j = 0; j < 4; j++)
                #pragma unroll
                for (int q = 0; q < 4; q++) c2[j][q] = 0.f;

            const u32 a2h = s2u(xh + (mi2 * 16 + arow) * XR + kg * 32 + akof);
            const u32 a2l = s2u(xl + (mi2 * 16 + arow) * XR + kg * 32 + akof);
            const u32 b2h = s2u(smc + OB_W2H) + bofs264 + kg * 64;
            const u32 b2l = s2u(smc + OB_W2L) + bofs264 + kg * 64;

            #pragma unroll
            for (int kc = 0; kc < 2; kc++) {
                const u32 kb = kc * 32;
                u32 ah[4], al[4], bh0[4], bh1[4], bl0[4], bl1[4];
                ldsm4(ah, a2h + kb);
                ldsm4(al, a2l + kb);
                ldsm4(bh0, b2h + kb);
                ldsm4(bh1, b2h + kb + 16 * W2R * 2);
                ldsm4(bl0, b2l + kb);
                ldsm4(bl1, b2l + kb + 16 * W2R * 2);
                mma16(c2[0], ah, bh0[0], bh0[1]); mma16(c2[1], ah, bh0[2], bh0[3]);
                mma16(c2[2], ah, bh1[0], bh1[1]); mma16(c2[3], ah, bh1[2], bh1[3]);
                mma16(c2[0], ah, bl0[0], bl0[1]); mma16(c2[1], ah, bl0[2], bl0[3]);
                mma16(c2[2], ah, bl1[0], bl1[1]); mma16(c2[3], ah, bl1[2], bl1[3]);
                mma16(c2[0], al, bh0[0], bh0[1]); mma16(c2[1], al, bh0[2], bh0[3]);
                mma16(c2[2], al, bh1[0], bh1[1]); mma16(c2[3], al, bh1[2], bh1[3]);
            }
            // store partials: rs[kg][row][col]
            #pragma unroll
            for (int j = 0; j < 4; j++) {
                float* dst = rs + (kg * 32 + mi2 * 16 + gid) * 36 + j * 8 + 2 * tg;
                float2 lo; lo.x = c2[j][0]; lo.y = c2[j][1];
                float2 hi; hi.x = c2[j][2]; hi.y = c2[j][3];
                *(float2*)dst = lo;
                *(float2*)(dst + 8 * 36) = hi;
            }
        }
        __syncthreads();   // C: partials ready

        // ---- split-k reduce -> logits (warp w owns rows 2w, 2w+1) ----
        {
            int rrow = 2 * w + (l >> 4);
            int cc = (l & 15) * 2;
            float2 sum; sum.x = b2s[cc]; sum.y = b2s[cc + 1];
            #pragma unroll
            for (int kg2 = 0; kg2 < 8; kg2++) {
                float2 v = *(const float2*)(rs + (kg2 * 32 + rrow) * 36 + cc);
                sum.x += v.x; sum.y += v.y;
            }
            *(float2*)(lg + rrow * SLG + cc) = sum;
        }
        __syncwarp();

        // ---- softmax + last-write-wins scatter + out ----
        {
            float* y = yb + w * 64;
            unsigned mset = __match_any_sync(0xffffffffu, idxv);
            bool leader = (31 - __clz(mset)) == l;
            #pragma unroll
            for (int rr = 0; rr < 2; rr++) {
                int row = w * 2 + rr;
                float v = lg[row * SLG + l];
                float m = v;
                #pragma unroll
                for (int off = 16; off > 0; off >>= 1)
                    m = fmaxf(m, __shfl_xor_sync(0xffffffffu, m, off));
                float e = __expf(v - m);
                float ssum = e;
                #pragma unroll
                for (int off = 16; off > 0; off >>= 1)
                    ssum += __shfl_xor_sync(0xffffffffu, ssum, off);
                float p = e / ssum;
                y[l] = 0.f; y[l + 32] = 0.f;
                __syncwarp();
                if (leader) y[idxv] = p;
                __syncwarp();
                float* op = out + (size_t)(rowbase + row) * (Tst * Vt) + (size_t)t * Vt;
                *(float2*)(op + 2 * l) = *(const float2*)(y + 2 * l);
                __syncwarp();
            }
        }
        // next-step smem writes gated by barriers A/B/C of next iteration
    }
}

extern "C" void kernel_launch(void* const* d_in, const int* in_sizes, int n_in,
                              void* d_out, int out_size)
{
    const float* latent0   = (const float*)d_in[0];
    const float* W1        = (const float*)d_in[1];
    const float* b1        = (const float*)d_in[2];
    const float* W2        = (const float*)d_in[3];
    const float* b2        = (const float*)d_in[4];
    const int*   state_seq = (const int*)  d_in[5];
    const int*   out_idx   = (const int*)  d_in[6];
    float* out = (float*)d_out;

    split_w12<<<2048, 512>>>(W1, W2);

    cudaFuncSetAttribute(lalr_all, cudaFuncAttributeMaxDynamicSharedMemorySize, SMEMB);
    lalr_all<<<Bsz / MT, 512, SMEMB>>>(
        latent0, W1, b1, W2, b2, state_seq, out_idx, out);
}

// round 9
// speedup vs baseline: 2.7923x; 1.0126x over previous
#include <cuda_runtime.h>
#include <cuda_bf16.h>
#include <cstdint>

#define Bsz 4096
#define Tst 128
#define NL  256
#define NSt 64
#define NOt 32
#define Vt  64
#define MT  32
#define XR  264        // x row stride (bf16)
#define NCH 16
#define SLG 36
#define W2R 264        // w2 smem row stride (bf16)

typedef unsigned long long ull;
typedef uint32_t u32;

__device__ __nv_bfloat16 g_w1h[(size_t)NSt * NL * NL];
__device__ __nv_bfloat16 g_w1l[(size_t)NSt * NL * NL];
__device__ __nv_bfloat16 g_w2h[(size_t)NSt * NOt * NL];
__device__ __nv_bfloat16 g_w2l[(size_t)NSt * NOt * NL];

__device__ __forceinline__ u32 s2u(const void* p) {
    return (u32)__cvta_generic_to_shared(p);
}
__device__ __forceinline__ void ldsm4(u32* r, u32 a) {
    asm volatile("ldmatrix.sync.aligned.m8n8.x4.shared.b16 {%0,%1,%2,%3}, [%4];"
        : "=r"(r[0]), "=r"(r[1]), "=r"(r[2]), "=r"(r[3]) : "r"(a));
}
__device__ __forceinline__ void mma16(float* c, const u32* a, u32 b0, u32 b1) {
    asm volatile("mma.sync.aligned.m16n8k16.row.col.f32.bf16.bf16.f32 "
        "{%0,%1,%2,%3},{%4,%5,%6,%7},{%8,%9},{%0,%1,%2,%3};"
        : "+f"(c[0]), "+f"(c[1]), "+f"(c[2]), "+f"(c[3])
        : "r"(a[0]), "r"(a[1]), "r"(a[2]), "r"(a[3]), "r"(b0), "r"(b1));
}
__device__ __forceinline__ void cpa16(u32 dst, const void* src) {
    asm volatile("cp.async.cg.shared.global [%0], [%1], 16;"
        :: "r"(dst), "l"(src) : "memory");
}
#define CPA_COMMIT() asm volatile("cp.async.commit_group;" ::: "memory")
#define CPA_WAIT1()  asm volatile("cp.async.wait_group 1;" ::: "memory")

__device__ __forceinline__ void sp(__nv_bfloat16* xh, __nv_bfloat16* xl, int idx,
                                   float v0, float v1) {
    __nv_bfloat16 h0 = __float2bfloat16(v0), h1 = __float2bfloat16(v1);
    __nv_bfloat162 hp; hp.x = h0; hp.y = h1;
    *(__nv_bfloat162*)(xh + idx) = hp;
    __nv_bfloat162 lp;
    lp.x = __float2bfloat16(v0 - __bfloat162float(h0));
    lp.y = __float2bfloat16(v1 - __bfloat162float(h1));
    *(__nv_bfloat162*)(xl + idx) = lp;
}

// smem byte offsets
#define OB_XH0 0                 // [32][XR] bf16  16896
#define OB_XL0 16896
#define OB_XH1 33792             // second x buffer
#define OB_XL1 50688
#define OB_W1S 67584             // 16w x 4stage x 2arr x 768B = 98304
#define OB_W2H 165888            // 16896
#define OB_W2L 182784            // 16896
#define OB_RS  199680            // [4][32][36] f32 = 18432
#define OB_LG  218112            // 4608
#define OB_YB  222720            // 4096
#define OB_B2  226816            // 2 x 32 f32 = 256 (double-buffered)
#define OB_SQ  227072            // 512
#define SMEMB  227584

__global__ void split_w12(const float* __restrict__ W1, const float* __restrict__ W2) {
    const size_t n1 = (size_t)NSt * NL * NL;
    for (size_t i = blockIdx.x * blockDim.x + threadIdx.x; i < n1;
         i += (size_t)gridDim.x * blockDim.x) {
        float x = W1[i];
        __nv_bfloat16 h = __float2bfloat16(x);
        g_w1h[i] = h;
        g_w1l[i] = __float2bfloat16(x - __bfloat162float(h));
    }
    const size_t n2 = (size_t)NSt * NOt * NL;
    for (size_t i = blockIdx.x * blockDim.x + threadIdx.x; i < n2;
         i += (size_t)gridDim.x * blockDim.x) {
        float x = W2[i];
        __nv_bfloat16 h = __float2bfloat16(x);
        g_w2h[i] = h;
        g_w2l[i] = __float2bfloat16(x - __bfloat162float(h));
    }
}

__global__ void __launch_bounds__(512, 1) lalr_all(
    const float* __restrict__ latent0,
    const float* __restrict__ W1, const float* __restrict__ b1,
    const float* __restrict__ W2, const float* __restrict__ b2,
    const int*   __restrict__ state_seq, const int* __restrict__ out_idx,
    float* __restrict__ out)
{
    extern __shared__ char smc[];
    float* rs  = (float*)(smc + OB_RS);
    float* lg  = (float*)(smc + OB_LG);
    float* yb  = (float*)(smc + OB_YB);
    float* b2s = (float*)(smc + OB_B2);   // [2][32]
    int*  sseq = (int*)(smc + OB_SQ);

    const int tid = threadIdx.x;
    const int w = tid >> 5, l = tid & 31;
    const int rowbase = blockIdx.x * MT;
    const int gid = l >> 2, tg = l & 3;

    // ldmatrix lane mappings (proven idioms)
    const int arow = l & 15;
    const int akof = (l >> 4) * 8;
    const int bn   = ((l >> 4) & 1) * 8 + (l & 7);
    const int bk   = (l >> 3) & 1;
    const int bofs24  = (bn * 24  + bk * 8) * 2;
    const int bofs264 = (bn * W2R + bk * 8) * 2;
    // W1 cp.async fill mapping
    const int fn = l & 15;
    const int fk = (l >> 4) * 8;
    const int stsofs = (fn * 24 + fk) * 2;
    const u32 wstage = s2u(smc + OB_W1S + w * 6144);
    char* wbase = smc + OB_W1S + w * 6144;
    // W2 fill mapping
    const int o2 = tid & 31, kq2 = (tid >> 5) * 16;
    // GEMM2 warp roles: (mi2, nh, kg)
    const int mi2 = w & 1, nh = (w >> 1) & 1, kg = w >> 2;

    // ---- init ----
    if (tid < Tst) sseq[tid] = state_seq[tid];
    {
        __nv_bfloat16* xh0 = (__nv_bfloat16*)(smc + OB_XH0);
        __nv_bfloat16* xl0 = (__nv_bfloat16*)(smc + OB_XL0);
        int r = tid >> 4, kc = (tid & 15) * 16;
        const float* src = latent0 + (size_t)(rowbase + r) * NL + kc;
        #pragma unroll
        for (int j = 0; j < 16; j += 2)
            sp(xh0 + r * XR + kc, xl0 + r * XR + kc, j, src[j], src[j + 1]);
    }
    __syncthreads();

    // W1 chunk issuer: global chunk ig -> stage ig&3
    auto issue_w1 = [&](int ig) {
        if (ig < Tst * NCH) {
            int sg = sseq[(ig >> 4) & (Tst - 1)];
            int kc = (ig & 15) << 4;
            size_t off = ((size_t)sg * NL + w * 16 + fn) * NL + kc + fk;
            u32 dh = wstage + (ig & 3) * 1536 + stsofs;
            cpa16(dh, g_w1h + off);
            cpa16(dh + 768, g_w1l + off);
        }
        CPA_COMMIT();
    };
    issue_w1(0); issue_w1(1); issue_w1(2);

    // ---- prologue loads for t=0 ----
    int s = sseq[0];
    const __nv_bfloat16* w2hsrc = g_w2h + ((size_t)s * NOt + o2) * NL + kq2;
    const __nv_bfloat16* w2lsrc = g_w2l + ((size_t)s * NOt + o2) * NL + kq2;
    uint4 qh0 = *(const uint4*)(w2hsrc);
    uint4 qh1 = *(const uint4*)(w2hsrc + 8);
    uint4 ql0 = *(const uint4*)(w2lsrc);
    uint4 ql1 = *(const uint4*)(w2lsrc + 8);
    float b2r = (tid < NOt) ? b2[s * NOt + tid] : 0.f;

    for (int t = 0; t < Tst; t++) {
        char* xcb = smc + (t & 1) * 33792;         // current x buffer (XH0/XL0 or XH1/XL1)
        char* xnb = smc + ((t & 1) ^ 1) * 33792;   // next x buffer
        __nv_bfloat16* xh_c = (__nv_bfloat16*)(xcb + OB_XH0);
        __nv_bfloat16* xl_c = (__nv_bfloat16*)(xcb + OB_XL0);
        __nv_bfloat16* xh_n = (__nv_bfloat16*)(xnb + OB_XH0);
        __nv_bfloat16* xl_n = (__nv_bfloat16*)(xnb + OB_XL0);

        float2 bias0 = *(const float2*)(b1 + s * NL + w * 16 + 2 * tg);
        float2 bias1 = *(const float2*)(b1 + s * NL + w * 16 + 8 + 2 * tg);
        int idxv = out_idx[s * NOt + l];

        // W2 -> smem [o][W2R] bf16 h/l; b2 -> double-buffered smem
        {
            char* dh = smc + OB_W2H + (o2 * W2R + kq2) * 2;
            char* dl = smc + OB_W2L + (o2 * W2R + kq2) * 2;
            *(uint4*)(dh) = qh0; *(uint4*)(dh + 16) = qh1;
            *(uint4*)(dl) = ql0; *(uint4*)(dl + 16) = ql1;
        }
        if (tid < NOt) b2s[(t & 1) * 32 + tid] = b2r;
        __syncwarp();

        // ---- GEMM1: 3-term bf16 split MMA, pair-pipelined cp.async W1 ----
        float acc[2][2][4];
        #pragma unroll
        for (int mi = 0; mi < 2; mi++)
            #pragma unroll
            for (int ni = 0; ni < 2; ni++)
                #pragma unroll
                for (int j = 0; j < 4; j++) acc[mi][ni][j] = 0.f;

        const u32 aHb = s2u(xh_c + arow * XR + akof);
        const u32 aLb = s2u(xl_c + arow * XR + akof);

        #pragma unroll 2
        for (int kt = 0; kt < NCH; kt += 2) {
            const int g = t * NCH + kt;
            CPA_WAIT1();          // chunks g and g+1 complete
            __syncwarp();

            // ---- chunk g ----
            {
                const u32 ka = kt * 32;
                u32 ah0[4], ah1[4], al0[4], al1[4], bh[4], bl[4];
                ldsm4(ah0, aHb + ka);
                ldsm4(ah1, aHb + ka + 16 * XR * 2);
                ldsm4(al0, aLb + ka);
                ldsm4(al1, aLb + ka + 16 * XR * 2);
                char* wb = wbase + (g & 3) * 1536;
                ldsm4(bh, s2u(wb) + bofs24);
                ldsm4(bl, s2u(wb + 768) + bofs24);
                issue_w1(g + 3);
                mma16(acc[0][0], ah0, bh[0], bh[1]); mma16(acc[0][1], ah0, bh[2], bh[3]);
                mma16(acc[1][0], ah1, bh[0], bh[1]); mma16(acc[1][1], ah1, bh[2], bh[3]);
                mma16(acc[0][0], ah0, bl[0], bl[1]); mma16(acc[0][1], ah0, bl[2], bl[3]);
                mma16(acc[1][0], ah1, bl[0], bl[1]); mma16(acc[1][1], ah1, bl[2], bl[3]);
                mma16(acc[0][0], al0, bh[0], bh[1]); mma16(acc[0][1], al0, bh[2], bh[3]);
                mma16(acc[1][0], al1, bh[0], bh[1]); mma16(acc[1][1], al1, bh[2], bh[3]);
            }
            // ---- chunk g+1 (issue g+4 only after chunk g's mma: stage reuse safe) ----
            {
                const u32 ka = kt * 32 + 32;
                u32 ah0[4], ah1[4], al0[4], al1[4], bh[4], bl[4];
                ldsm4(ah0, aHb + ka);
                ldsm4(ah1, aHb + ka + 16 * XR * 2);
                ldsm4(al0, aLb + ka);
                ldsm4(al1, aLb + ka + 16 * XR * 2);
                char* wb = wbase + ((g + 1) & 3) * 1536;
                ldsm4(bh, s2u(wb) + bofs24);
                ldsm4(bl, s2u(wb + 768) + bofs24);
                issue_w1(g + 4);
                mma16(acc[0][0], ah0, bh[0], bh[1]); mma16(acc[0][1], ah0, bh[2], bh[3]);
                mma16(acc[1][0], ah1, bh[0], bh[1]); mma16(acc[1][1], ah1, bh[2], bh[3]);
                mma16(acc[0][0], ah0, bl[0], bl[1]); mma16(acc[0][1], ah0, bl[2], bl[3]);
                mma16(acc[1][0], ah1, bl[0], bl[1]); mma16(acc[1][1], ah1, bl[2], bl[3]);
                mma16(acc[0][0], al0, bh[0], bh[1]); mma16(acc[0][1], al0, bh[2], bh[3]);
                mma16(acc[1][0], al1, bh[0], bh[1]); mma16(acc[1][1], al1, bh[2], bh[3]);
            }
        }

        // ---- tail prefetch for t+1 ----
        s = sseq[(t + 1) & (Tst - 1)];
        w2hsrc = g_w2h + ((size_t)s * NOt + o2) * NL + kq2;
        w2lsrc = g_w2l + ((size_t)s * NOt + o2) * NL + kq2;
        qh0 = *(const uint4*)(w2hsrc);
        qh1 = *(const uint4*)(w2hsrc + 8);
        ql0 = *(const uint4*)(w2lsrc);
        ql1 = *(const uint4*)(w2lsrc + 8);
        b2r = (tid < NOt) ? b2[s * NOt + tid] : 0.f;

        // ---- epilogue: tanh + bf16 split -> NEXT x buffer (no barrier needed) ----
        #pragma unroll
        for (int mi = 0; mi < 2; mi++)
            #pragma unroll
            for (int ni = 0; ni < 2; ni++) {
                float2 bias = ni ? bias1 : bias0;
                float* c = acc[mi][ni];
                int cp = w * 16 + ni * 8 + 2 * tg;
                int r0 = mi * 16 + gid;
                sp(xh_n, xl_n, r0 * XR + cp, tanhf(c[0] + bias.x), tanhf(c[1] + bias.y));
                sp(xh_n, xl_n, (r0 + 8) * XR + cp, tanhf(c[2] + bias.x), tanhf(c[3] + bias.y));
            }
        __syncthreads();   // B: x_{t+1} + w2/b2 smem ready

        // ---- GEMM2 via MMA: warp = m16(mi2) x n16(nh) x k64(kg), 3-term ----
        {
            float c2[2][4];
            #pragma unroll
            for (int j = 0; j < 2; j++)
                #pragma unroll
                for (int q = 0; q < 4; q++) c2[j][q] = 0.f;

            const u32 a2h = s2u(xh_n + (mi2 * 16 + arow) * XR + kg * 64 + akof);
            const u32 a2l = s2u(xl_n + (mi2 * 16 + arow) * XR + kg * 64 + akof);
            const u32 b2hB = s2u(smc + OB_W2H) + nh * 16 * W2R * 2 + bofs264 + kg * 128;
            const u32 b2lB = s2u(smc + OB_W2L) + nh * 16 * W2R * 2 + bofs264 + kg * 128;

            #pragma unroll
            for (int kc = 0; kc < 4; kc++) {
                const u32 kb = kc * 32;
                u32 ah[4], al[4], bh[4], bl[4];
                ldsm4(ah, a2h + kb);
                ldsm4(al, a2l + kb);
                ldsm4(bh, b2hB + kb);
                ldsm4(bl, b2lB + kb);
                mma16(c2[0], ah, bh[0], bh[1]); mma16(c2[1], ah, bh[2], bh[3]);
                mma16(c2[0], ah, bl[0], bl[1]); mma16(c2[1], ah, bl[2], bl[3]);
                mma16(c2[0], al, bh[0], bh[1]); mma16(c2[1], al, bh[2], bh[3]);
            }
            // store partials: rs[kg][row][col], col = nh*16 + j*8 + 2tg
            #pragma unroll
            for (int j = 0; j < 2; j++) {
                float* dst = rs + (kg * 32 + mi2 * 16 + gid) * 36 + nh * 16 + j * 8 + 2 * tg;
                float2 lo; lo.x = c2[j][0]; lo.y = c2[j][1];
                float2 hi; hi.x = c2[j][2]; hi.y = c2[j][3];
                *(float2*)dst = lo;
                *(float2*)(dst + 8 * 36) = hi;
            }
        }
        __syncthreads();   // C: partials ready

        // ---- split-k reduce -> logits (warp w owns rows 2w, 2w+1) ----
        {
            int rrow = 2 * w + (l >> 4);
            int cc = (l & 15) * 2;
            const float* bb = b2s + (t & 1) * 32;
            float2 sum; sum.x = bb[cc]; sum.y = bb[cc + 1];
            #pragma unroll
            for (int kg2 = 0; kg2 < 4; kg2++) {
                float2 v = *(const float2*)(rs + (kg2 * 32 + rrow) * 36 + cc);
                sum.x += v.x; sum.y += v.y;
            }
            *(float2*)(lg + rrow * SLG + cc) = sum;
        }
        __syncwarp();

        // ---- softmax + last-write-wins scatter + out ----
        {
            float* y = yb + w * 64;
            unsigned mset = __match_any_sync(0xffffffffu, idxv);
            bool leader = (31 - __clz(mset)) == l;
            #pragma unroll
            for (int rr = 0; rr < 2; rr++) {
                int row = w * 2 + rr;
                float v = lg[row * SLG + l];
                float m = v;
                #pragma unroll
                for (int off = 16; off > 0; off >>= 1)
                    m = fmaxf(m, __shfl_xor_sync(0xffffffffu, m, off));
                float e = __expf(v - m);
                float ssum = e;
                #pragma unroll
                for (int off = 16; off > 0; off >>= 1)
                    ssum += __shfl_xor_sync(0xffffffffu, ssum, off);
                float p = e / ssum;
                y[l] = 0.f; y[l + 32] = 0.f;
                __syncwarp();
                if (leader) y[idxv] = p;
                __syncwarp();
                float* op = out + (size_t)(rowbase + row) * (Tst * Vt) + (size_t)t * Vt;
                *(float2*)(op + 2 * l) = *(const float2*)(y + 2 * l);
                __syncwarp();
            }
        }
    }
}

extern "C" void kernel_launch(void* const* d_in, const int* in_sizes, int n_in,
                              void* d_out, int out_size)
{
    const float* latent0   = (const float*)d_in[0];
    const float* W1        = (const float*)d_in[1];
    const float* b1        = (const float*)d_in[2];
    const float* W2        = (const float*)d_in[3];
    const float* b2        = (const float*)d_in[4];
    const int*   state_seq = (const int*)  d_in[5];
    const int*   out_idx   = (const int*)  d_in[6];
    float* out = (float*)d_out;

    split_w12<<<2048, 512>>>(W1, W2);

    cudaFuncSetAttribute(lalr_all, cudaFuncAttributeMaxDynamicSharedMemorySize, SMEMB);
    lalr_all<<<Bsz / MT, 512, SMEMB>>>(
        latent0, W1, b1, W2, b2, state_seq, out_idx, out);
}

// round 10
// speedup vs baseline: 2.8087x; 1.0059x over previous
#include <cuda_runtime.h>
#include <cuda_bf16.h>
#include <cstdint>

#define Bsz 4096
#define Tst 128
#define NL  256
#define NSt 64
#define NOt 32
#define Vt  64
#define MT  32
#define XR  264        // x row stride (bf16)
#define NCH 16
#define SLG 36
#define W2R 264        // w2 smem row stride (bf16)

typedef unsigned long long ull;
typedef uint32_t u32;

__device__ __nv_bfloat16 g_w1h[(size_t)NSt * NL * NL];
__device__ __nv_bfloat16 g_w1l[(size_t)NSt * NL * NL];
__device__ __nv_bfloat16 g_w2h[(size_t)NSt * NOt * NL];
__device__ __nv_bfloat16 g_w2l[(size_t)NSt * NOt * NL];

__device__ __forceinline__ u32 s2u(const void* p) {
    return (u32)__cvta_generic_to_shared(p);
}
__device__ __forceinline__ void ldsm4(u32* r, u32 a) {
    asm volatile("ldmatrix.sync.aligned.m8n8.x4.shared.b16 {%0,%1,%2,%3}, [%4];"
        : "=r"(r[0]), "=r"(r[1]), "=r"(r[2]), "=r"(r[3]) : "r"(a));
}
__device__ __forceinline__ void mma16(float* c, const u32* a, u32 b0, u32 b1) {
    asm volatile("mma.sync.aligned.m16n8k16.row.col.f32.bf16.bf16.f32 "
        "{%0,%1,%2,%3},{%4,%5,%6,%7},{%8,%9},{%0,%1,%2,%3};"
        : "+f"(c[0]), "+f"(c[1]), "+f"(c[2]), "+f"(c[3])
        : "r"(a[0]), "r"(a[1]), "r"(a[2]), "r"(a[3]), "r"(b0), "r"(b1));
}
__device__ __forceinline__ void cpa16(u32 dst, const void* src) {
    asm volatile("cp.async.cg.shared.global [%0], [%1], 16;"
        :: "r"(dst), "l"(src) : "memory");
}
#define CPA_COMMIT() asm volatile("cp.async.commit_group;" ::: "memory")
#define CPA_WAIT1()  asm volatile("cp.async.wait_group 1;" ::: "memory")

// Fast branch-free tanh: |abs err| <~ 2^-21, no overflow (t in (0,1]).
__device__ __forceinline__ float ftanh(float x) {
    float t = __expf(-2.f * fabsf(x));
    float r = __fdividef(1.f - t, 1.f + t);
    return copysignf(r, x);
}

__device__ __forceinline__ void sp(__nv_bfloat16* xh, __nv_bfloat16* xl, int idx,
                                   float v0, float v1) {
    __nv_bfloat16 h0 = __float2bfloat16(v0), h1 = __float2bfloat16(v1);
    __nv_bfloat162 hp; hp.x = h0; hp.y = h1;
    *(__nv_bfloat162*)(xh + idx) = hp;
    __nv_bfloat162 lp;
    lp.x = __float2bfloat16(v0 - __bfloat162float(h0));
    lp.y = __float2bfloat16(v1 - __bfloat162float(h1));
    *(__nv_bfloat162*)(xl + idx) = lp;
}

// smem byte offsets
#define OB_XH0 0                 // [32][XR] bf16  16896
#define OB_XL0 16896
#define OB_XH1 33792             // second x buffer
#define OB_XL1 50688
#define OB_W1S 67584             // 16w x 4stage x 2arr x 768B = 98304
#define OB_W2H 165888            // 16896
#define OB_W2L 182784            // 16896
#define OB_RS  199680            // [4][32][36] f32 = 18432
#define OB_LG  218112            // 4608
#define OB_YB  222720            // 4096
#define OB_B2  226816            // 2 x 32 f32 (double-buffered)
#define OB_SQ  227072            // 512
#define SMEMB  227584

__global__ void split_w12(const float* __restrict__ W1, const float* __restrict__ W2) {
    const size_t n1 = (size_t)NSt * NL * NL;
    for (size_t i = blockIdx.x * blockDim.x + threadIdx.x; i < n1;
         i += (size_t)gridDim.x * blockDim.x) {
        float x = W1[i];
        __nv_bfloat16 h = __float2bfloat16(x);
        g_w1h[i] = h;
        g_w1l[i] = __float2bfloat16(x - __bfloat162float(h));
    }
    const size_t n2 = (size_t)NSt * NOt * NL;
    for (size_t i = blockIdx.x * blockDim.x + threadIdx.x; i < n2;
         i += (size_t)gridDim.x * blockDim.x) {
        float x = W2[i];
        __nv_bfloat16 h = __float2bfloat16(x);
        g_w2h[i] = h;
        g_w2l[i] = __float2bfloat16(x - __bfloat162float(h));
    }
}

__global__ void __launch_bounds__(512, 1) lalr_all(
    const float* __restrict__ latent0,
    const float* __restrict__ W1, const float* __restrict__ b1,
    const float* __restrict__ W2, const float* __restrict__ b2,
    const int*   __restrict__ state_seq, const int* __restrict__ out_idx,
    float* __restrict__ out)
{
    extern __shared__ char smc[];
    float* rs  = (float*)(smc + OB_RS);
    float* lg  = (float*)(smc + OB_LG);
    float* yb  = (float*)(smc + OB_YB);
    float* b2s = (float*)(smc + OB_B2);
    int*  sseq = (int*)(smc + OB_SQ);

    const int tid = threadIdx.x;
    const int w = tid >> 5, l = tid & 31;
    const int rowbase = blockIdx.x * MT;
    const int gid = l >> 2, tg = l & 3;

    // ldmatrix lane mappings (proven idioms)
    const int arow = l & 15;
    const int akof = (l >> 4) * 8;
    const int bn   = ((l >> 4) & 1) * 8 + (l & 7);
    const int bk   = (l >> 3) & 1;
    const int bofs24  = (bn * 24  + bk * 8) * 2;
    const int bofs264 = (bn * W2R + bk * 8) * 2;
    // W1 cp.async fill mapping
    const int fn = l & 15;
    const int fk = (l >> 4) * 8;
    const int stsofs = (fn * 24 + fk) * 2;
    const u32 wstage = s2u(smc + OB_W1S + w * 6144);
    char* wbase = smc + OB_W1S + w * 6144;
    // W2 fill mapping
    const int o2 = tid & 31, kq2 = (tid >> 5) * 16;
    // GEMM2 warp roles: (mi2, nh, kg)
    const int mi2 = w & 1, nh = (w >> 1) & 1, kg = w >> 2;

    // ---- init ----
    if (tid < Tst) sseq[tid] = state_seq[tid];
    {
        __nv_bfloat16* xh0 = (__nv_bfloat16*)(smc + OB_XH0);
        __nv_bfloat16* xl0 = (__nv_bfloat16*)(smc + OB_XL0);
        int r = tid >> 4, kc = (tid & 15) * 16;
        const float* src = latent0 + (size_t)(rowbase + r) * NL + kc;
        #pragma unroll
        for (int j = 0; j < 16; j += 2)
            sp(xh0 + r * XR + kc, xl0 + r * XR + kc, j, src[j], src[j + 1]);
    }
    __syncthreads();

    // W1 chunk issuer: global chunk ig -> stage ig&3; base = per-step elem offset
    auto issue_w1 = [&](int ig, size_t base) {
        if (ig < Tst * NCH) {
            u32 dh = wstage + (ig & 3) * 1536 + stsofs;
            size_t off = base + ((size_t)(ig & 15) << 4);
            cpa16(dh, g_w1h + off);
            cpa16(dh + 768, g_w1l + off);
        }
        CPA_COMMIT();
    };

    // ---- prologue loads for t=0 ----
    int s = sseq[0];
    size_t base_cur = ((size_t)s * NL + w * 16 + fn) * NL + fk;
    issue_w1(0, base_cur); issue_w1(1, base_cur); issue_w1(2, base_cur);

    const __nv_bfloat16* w2hsrc = g_w2h + ((size_t)s * NOt + o2) * NL + kq2;
    const __nv_bfloat16* w2lsrc = g_w2l + ((size_t)s * NOt + o2) * NL + kq2;
    uint4 qh0 = *(const uint4*)(w2hsrc);
    uint4 qh1 = *(const uint4*)(w2hsrc + 8);
    uint4 ql0 = *(const uint4*)(w2lsrc);
    uint4 ql1 = *(const uint4*)(w2lsrc + 8);
    float b2r = (tid < NOt) ? b2[s * NOt + tid] : 0.f;

    for (int t = 0; t < Tst; t++) {
        char* xcb = smc + (t & 1) * 33792;
        char* xnb = smc + ((t & 1) ^ 1) * 33792;
        __nv_bfloat16* xh_c = (__nv_bfloat16*)(xcb + OB_XH0);
        __nv_bfloat16* xl_c = (__nv_bfloat16*)(xcb + OB_XL0);
        __nv_bfloat16* xh_n = (__nv_bfloat16*)(xnb + OB_XH0);
        __nv_bfloat16* xl_n = (__nv_bfloat16*)(xnb + OB_XL0);

        float2 bias0 = *(const float2*)(b1 + s * NL + w * 16 + 2 * tg);
        float2 bias1 = *(const float2*)(b1 + s * NL + w * 16 + 8 + 2 * tg);
        int idxv = out_idx[s * NOt + l];

        // next-step state + W1 base (for cross-step chunk issues)
        const int s_nxt = sseq[(t + 1) & (Tst - 1)];
        const size_t base_nxt = ((size_t)s_nxt * NL + w * 16 + fn) * NL + fk;

        // W2 -> smem [o][W2R] bf16 h/l; b2 -> double-buffered smem
        {
            char* dh = smc + OB_W2H + (o2 * W2R + kq2) * 2;
            char* dl = smc + OB_W2L + (o2 * W2R + kq2) * 2;
            *(uint4*)(dh) = qh0; *(uint4*)(dh + 16) = qh1;
            *(uint4*)(dl) = ql0; *(uint4*)(dl + 16) = ql1;
        }
        if (tid < NOt) b2s[(t & 1) * 32 + tid] = b2r;
        __syncwarp();

        // ---- GEMM1: 3-term bf16 split MMA, pair-pipelined cp.async W1 ----
        float acc[2][2][4];
        #pragma unroll
        for (int mi = 0; mi < 2; mi++)
            #pragma unroll
            for (int ni = 0; ni < 2; ni++)
                #pragma unroll
                for (int j = 0; j < 4; j++) acc[mi][ni][j] = 0.f;

        const u32 aHb = s2u(xh_c + arow * XR + akof);
        const u32 aLb = s2u(xl_c + arow * XR + akof);

        #pragma unroll 2
        for (int kt = 0; kt < NCH; kt += 2) {
            const int g = t * NCH + kt;
            CPA_WAIT1();
            __syncwarp();

            // ---- chunk g ----
            {
                const u32 ka = kt * 32;
                u32 ah0[4], ah1[4], al0[4], al1[4], bh[4], bl[4];
                ldsm4(ah0, aHb + ka);
                ldsm4(ah1, aHb + ka + 16 * XR * 2);
                ldsm4(al0, aLb + ka);
                ldsm4(al1, aLb + ka + 16 * XR * 2);
                char* wb = wbase + (g & 3) * 1536;
                ldsm4(bh, s2u(wb) + bofs24);
                ldsm4(bl, s2u(wb + 768) + bofs24);
                issue_w1(g + 3, (kt + 3 < NCH) ? base_cur : base_nxt);
                mma16(acc[0][0], ah0, bh[0], bh[1]); mma16(acc[0][1], ah0, bh[2], bh[3]);
                mma16(acc[1][0], ah1, bh[0], bh[1]); mma16(acc[1][1], ah1, bh[2], bh[3]);
                mma16(acc[0][0], ah0, bl[0], bl[1]); mma16(acc[0][1], ah0, bl[2], bl[3]);
                mma16(acc[1][0], ah1, bl[0], bl[1]); mma16(acc[1][1], ah1, bl[2], bl[3]);
                mma16(acc[0][0], al0, bh[0], bh[1]); mma16(acc[0][1], al0, bh[2], bh[3]);
                mma16(acc[1][0], al1, bh[0], bh[1]); mma16(acc[1][1], al1, bh[2], bh[3]);
            }
            // ---- chunk g+1 ----
            {
                const u32 ka = kt * 32 + 32;
                u32 ah0[4], ah1[4], al0[4], al1[4], bh[4], bl[4];
                ldsm4(ah0, aHb + ka);
                ldsm4(ah1, aHb + ka + 16 * XR * 2);
                ldsm4(al0, aLb + ka);
                ldsm4(al1, aLb + ka + 16 * XR * 2);
                char* wb = wbase + ((g + 1) & 3) * 1536;
                ldsm4(bh, s2u(wb) + bofs24);
                ldsm4(bl, s2u(wb + 768) + bofs24);
                issue_w1(g + 4, (kt + 4 < NCH) ? base_cur : base_nxt);
                mma16(acc[0][0], ah0, bh[0], bh[1]); mma16(acc[0][1], ah0, bh[2], bh[3]);
                mma16(acc[1][0], ah1, bh[0], bh[1]); mma16(acc[1][1], ah1, bh[2], bh[3]);
                mma16(acc[0][0], ah0, bl[0], bl[1]); mma16(acc[0][1], ah0, bl[2], bl[3]);
                mma16(acc[1][0], ah1, bl[0], bl[1]); mma16(acc[1][1], ah1, bl[2], bl[3]);
                mma16(acc[0][0], al0, bh[0], bh[1]); mma16(acc[0][1], al0, bh[2], bh[3]);
                mma16(acc[1][0], al1, bh[0], bh[1]); mma16(acc[1][1], al1, bh[2], bh[3]);
            }
        }

        // ---- tail prefetch for t+1 (W2 h/l + b2) ----
        w2hsrc = g_w2h + ((size_t)s_nxt * NOt + o2) * NL + kq2;
        w2lsrc = g_w2l + ((size_t)s_nxt * NOt + o2) * NL + kq2;
        qh0 = *(const uint4*)(w2hsrc);
        qh1 = *(const uint4*)(w2hsrc + 8);
        ql0 = *(const uint4*)(w2lsrc);
        ql1 = *(const uint4*)(w2lsrc + 8);
        b2r = (tid < NOt) ? b2[s_nxt * NOt + tid] : 0.f;
        s = s_nxt;
        base_cur = base_nxt;

        // ---- epilogue: fast tanh + bf16 split -> NEXT x buffer ----
        #pragma unroll
        for (int mi = 0; mi < 2; mi++)
            #pragma unroll
            for (int ni = 0; ni < 2; ni++) {
                float2 bias = ni ? bias1 : bias0;
                float* c = acc[mi][ni];
                int cp = w * 16 + ni * 8 + 2 * tg;
                int r0 = mi * 16 + gid;
                sp(xh_n, xl_n, r0 * XR + cp, ftanh(c[0] + bias.x), ftanh(c[1] + bias.y));
                sp(xh_n, xl_n, (r0 + 8) * XR + cp, ftanh(c[2] + bias.x), ftanh(c[3] + bias.y));
            }
        __syncthreads();   // B: x_{t+1} + w2/b2 smem ready

        // ---- GEMM2 via MMA: warp = m16(mi2) x n16(nh) x k64(kg), 3-term ----
        {
            float c2[2][4];
            #pragma unroll
            for (int j = 0; j < 2; j++)
                #pragma unroll
                for (int q = 0; q < 4; q++) c2[j][q] = 0.f;

            const u32 a2h = s2u(xh_n + (mi2 * 16 + arow) * XR + kg * 64 + akof);
            const u32 a2l = s2u(xl_n + (mi2 * 16 + arow) * XR + kg * 64 + akof);
            const u32 b2hB = s2u(smc + OB_W2H) + nh * 16 * W2R * 2 + bofs264 + kg * 128;
            const u32 b2lB = s2u(smc + OB_W2L) + nh * 16 * W2R * 2 + bofs264 + kg * 128;

            #pragma unroll
            for (int kc = 0; kc < 4; kc++) {
                const u32 kb = kc * 32;
                u32 ah[4], al[4], bh[4], bl[4];
                ldsm4(ah, a2h + kb);
                ldsm4(al, a2l + kb);
                ldsm4(bh, b2hB + kb);
                ldsm4(bl, b2lB + kb);
                mma16(c2[0], ah, bh[0], bh[1]); mma16(c2[1], ah, bh[2], bh[3]);
                mma16(c2[0], ah, bl[0], bl[1]); mma16(c2[1], ah, bl[2], bl[3]);
                mma16(c2[0], al, bh[0], bh[1]); mma16(c2[1], al, bh[2], bh[3]);
            }
            #pragma unroll
            for (int j = 0; j < 2; j++) {
                float* dst = rs + (kg * 32 + mi2 * 16 + gid) * 36 + nh * 16 + j * 8 + 2 * tg;
                float2 lo; lo.x = c2[j][0]; lo.y = c2[j][1];
                float2 hi; hi.x = c2[j][2]; hi.y = c2[j][3];
                *(float2*)dst = lo;
                *(float2*)(dst + 8 * 36) = hi;
            }
        }
        __syncthreads();   // C: partials ready

        // ---- split-k reduce -> logits ----
        {
            int rrow = 2 * w + (l >> 4);
            int cc = (l & 15) * 2;
            const float* bb = b2s + (t & 1) * 32;
            float2 sum; sum.x = bb[cc]; sum.y = bb[cc + 1];
            #pragma unroll
            for (int kg2 = 0; kg2 < 4; kg2++) {
                float2 v = *(const float2*)(rs + (kg2 * 32 + rrow) * 36 + cc);
                sum.x += v.x; sum.y += v.y;
            }
            *(float2*)(lg + rrow * SLG + cc) = sum;
        }
        __syncwarp();

        // ---- softmax + last-write-wins scatter + out ----
        {
            float* y = yb + w * 64;
            unsigned mset = __match_any_sync(0xffffffffu, idxv);
            bool leader = (31 - __clz(mset)) == l;
            #pragma unroll
            for (int rr = 0; rr < 2; rr++) {
                int row = w * 2 + rr;
                float v = lg[row * SLG + l];
                float m = v;
                #pragma unroll
                for (int off = 16; off > 0; off >>= 1)
                    m = fmaxf(m, __shfl_xor_sync(0xffffffffu, m, off));
                float e = __expf(v - m);
                float ssum = e;
                #pragma unroll
                for (int off = 16; off > 0; off >>= 1)
                    ssum += __shfl_xor_sync(0xffffffffu, ssum, off);
                float p = e / ssum;
                y[l] = 0.f; y[l + 32] = 0.f;
                __syncwarp();
                if (leader) y[idxv] = p;
                __syncwarp();
                float* op = out + (size_t)(rowbase + row) * (Tst * Vt) + (size_t)t * Vt;
                *(float2*)(op + 2 * l) = *(const float2*)(y + 2 * l);
                __syncwarp();
            }
        }
    }
}

extern "C" void kernel_launch(void* const* d_in, const int* in_sizes, int n_in,
                              void* d_out, int out_size)
{
    const float* latent0   = (const float*)d_in[0];
    const float* W1        = (const float*)d_in[1];
    const float* b1        = (const float*)d_in[2];
    const float* W2        = (const float*)d_in[3];
    const float* b2        = (const float*)d_in[4];
    const int*   state_seq = (const int*)  d_in[5];
    const int*   out_idx   = (const int*)  d_in[6];
    float* out = (float*)d_out;

    split_w12<<<2048, 512>>>(W1, W2);

    cudaFuncSetAttribute(lalr_all, cudaFuncAttributeMaxDynamicSharedMemorySize, SMEMB);
    lalr_all<<<Bsz / MT, 512, SMEMB>>>(
        latent0, W1, b1, W2, b2, state_seq, out_idx, out);
}